// round 13
// baseline (speedup 1.0000x reference)
#include <cuda_runtime.h>
#include <cuda_bf16.h>
#include <math.h>
#include <cstdint>

#define BATCH  4096
#define NIN    32
#define NHID   128
#define NOUT   30000
#define NCLUST 10000
#define BN_EPS 1e-3f

#define NCC      20000
#define NCC_PAD  20480
#define NBLK     313
#define NROWT    32
#define NUNITS   (NBLK * NROWT)     // 10016
#define NCTA     148

// ---- scratch ----
__device__ float g_h[BATCH * NHID];
__device__ float g_sum[NHID];
__device__ float g_sumsq[NHID];
__device__ float g_scale[NHID];
__device__ float g_shift[NHID];
__device__ __nv_bfloat16 g_Ah[BATCH * NHID];
__device__ __nv_bfloat16 g_Al[BATCH * NHID];
__device__ __nv_bfloat16 g_Bh[NCC_PAD * NHID];
__device__ __nv_bfloat16 g_Bl[NCC_PAD * NHID];
__device__ float2 g_b2p[10240];

// ---- MUFU-free exp / rcp ----------------------------------------------------
__device__ __forceinline__ float fexp(float x) {
    float t  = x * 1.4426950408889634f;
    float rf = t + 12582912.0f;
    int   ri = __float_as_int(rf) - 0x4B400000;
    float f  = t - (rf - 12582912.0f);
    float p = 1.3333558e-3f;
    p = fmaf(p, f, 9.6181291e-3f);
    p = fmaf(p, f, 5.5504109e-2f);
    p = fmaf(p, f, 2.4022651e-1f);
    p = fmaf(p, f, 6.9314718e-1f);
    p = fmaf(p, f, 1.0f);
    return __int_as_float(__float_as_int(p) + (ri << 23));
}
__device__ __forceinline__ float frcp(float d) {
    float r = __int_as_float(0x7EF127EAu - __float_as_int(d));
    #pragma unroll
    for (int i = 0; i < 2; i++) {
        float e = fmaf(-d, r, 1.0f);
        r = fmaf(r, e, r);
    }
    return r;
}

__device__ __forceinline__ uint32_t smem_u32(const void* p) {
    uint32_t a;
    asm("{ .reg .u64 t; cvta.to.shared.u64 t, %1; cvt.u32.u64 %0, t; }"
        : "=r"(a) : "l"(p));
    return a;
}
__device__ __forceinline__ void ldsm_x4(uint32_t& r0, uint32_t& r1,
                                        uint32_t& r2, uint32_t& r3, uint32_t a) {
    asm volatile("ldmatrix.sync.aligned.m8n8.x4.shared.b16 {%0,%1,%2,%3}, [%4];"
                 : "=r"(r0), "=r"(r1), "=r"(r2), "=r"(r3) : "r"(a));
}
__device__ __forceinline__ void mma16816(float* c, const uint32_t* a,
                                         const uint32_t* b) {
    asm volatile("mma.sync.aligned.m16n8k16.row.col.f32.bf16.bf16.f32 "
                 "{%0,%1,%2,%3}, {%4,%5,%6,%7}, {%8,%9}, {%0,%1,%2,%3};"
                 : "+f"(c[0]), "+f"(c[1]), "+f"(c[2]), "+f"(c[3])
                 : "r"(a[0]), "r"(a[1]), "r"(a[2]), "r"(a[3]),
                   "r"(b[0]), "r"(b[1]));
}
#define BAR_SYNC(id, cnt)   asm volatile("bar.sync %0, %1;"   :: "r"(id), "r"(cnt) : "memory")
#define BAR_ARRIVE(id, cnt) asm volatile("bar.arrive %0, %1;" :: "r"(id), "r"(cnt) : "memory")

// ---------------------------------------------------------------------------
__global__ void k_init() {
    int i = threadIdx.x;
    if (i < NHID) { g_sum[i] = 0.0f; g_sumsq[i] = 0.0f; }
}

__global__ void k_h(const float* __restrict__ z,
                    const float* __restrict__ W1,
                    const float* __restrict__ b1) {
    __shared__ float zs[128][33];
    __shared__ float ws[128][33];
    __shared__ float ps[2][128];
    __shared__ float psq[2][128];

    const int tid   = threadIdx.x;
    const int rbase = blockIdx.x * 128;

    for (int idx = tid; idx < 128 * NIN; idx += 256) {
        int r = idx >> 5, k = idx & 31;
        zs[r][k] = z[(rbase + r) * NIN + k];
        ws[r][k] = W1[idx];
    }
    __syncthreads();

    const int col = tid & 127;
    const int rh  = tid >> 7;
    const float bb = b1[col];
    float ls = 0.0f, lsq = 0.0f;

    for (int r = rh * 64; r < rh * 64 + 64; r++) {
        float acc = bb;
        #pragma unroll
        for (int k = 0; k < NIN; k++)
            acc = fmaf(zs[r][k], ws[col][k], acc);
        g_h[(rbase + r) * NHID + col] = acc;
        ls += acc;
        lsq = fmaf(acc, acc, lsq);
    }
    ps[rh][col]  = ls;
    psq[rh][col] = lsq;
    __syncthreads();
    if (tid < 128) {
        atomicAdd(&g_sum[tid],   ps[0][tid]  + ps[1][tid]);
        atomicAdd(&g_sumsq[tid], psq[0][tid] + psq[1][tid]);
    }
}

__global__ void k_bn(const float* __restrict__ gamma,
                     const float* __restrict__ beta) {
    int c = threadIdx.x;
    if (c >= NHID) return;
    const float inv_b = 1.0f / (float)BATCH;
    float mu   = g_sum[c] * inv_b;
    float var  = g_sumsq[c] * inv_b - mu * mu;
    float rstd = rsqrtf(var + BN_EPS);
    float sc   = gamma[c] * rstd;
    g_scale[c] = sc;
    g_shift[c] = beta[c] - mu * sc;
}

__global__ void k_split_h() {
    const int idx = blockIdx.x * 256 + threadIdx.x;
    if (idx >= BATCH * NHID) return;
    const int k = idx & 127;
    float v = fmaxf(fmaf(g_h[idx], g_scale[k], g_shift[k]), 0.0f);
    __nv_bfloat16 hi = __float2bfloat16_rn(v);
    g_Ah[idx] = hi;
    g_Al[idx] = __float2bfloat16_rn(v - __bfloat162float(hi));
}

__global__ void k_split_w(const float* __restrict__ W2,
                          const float* __restrict__ b2) {
    const int idx = blockIdx.x * 256 + threadIdx.x;
    if (idx < 10240) {
        float2 bp = make_float2(0.0f, 0.0f);
        if (idx < NCLUST)
            bp = make_float2(b2[3 * idx + 1], b2[3 * idx + 2]);
        g_b2p[idx] = bp;
    }
    if (idx >= NCC_PAD * NHID) return;
    const int cc = idx >> 7;
    const int k  = idx & 127;
    float w = 0.0f;
    if (cc < NCC) {
        const int c = cc >> 1, j = cc & 1;
        w = W2[(size_t)(3 * c + 1 + j) * NHID + k];
    }
    __nv_bfloat16 hi = __float2bfloat16_rn(w);
    g_Bh[idx] = hi;
    g_Bl[idx] = __float2bfloat16_rn(w - __bfloat162float(hi));
}

// ---------------------------------------------------------------------------
// k_gemm: warp-specialized producer/consumer, 512 thr, 1 CTA/SM, 148 CTAs.
// Producers (warps 0-7): ldsm + mma, dump fp32 acc to double-buffered slot.
// Consumers (warps 8-15): softmax epilogue + coalesced __stcs output.
// ---------------------------------------------------------------------------
#define LDA    136
#define LDS_SL 100            // slot row stride in floats

#define OFF_AH 0              // 34816 B
#define OFF_AL 34816
#define OFF_BH 69632          // 17408 B
#define OFF_BL 87040
#define OFF_S0 104448         // 51200 B each slot
#define OFF_S1 155648
#define SMEM_DYN 206848

// named barriers
#define BID_FULL0 1
#define BID_FULL1 2
#define BID_FREE0 3
#define BID_FREE1 4
#define BID_PROD  5
#define BID_CONS  6

extern "C" __global__ void __launch_bounds__(512, 1)
k_gemm(float* __restrict__ out) {
    extern __shared__ char sm[];
    const int tid = threadIdx.x;
    const int wid = tid >> 5;
    const int lid = tid & 31;
    const uint32_t smB = smem_u32(sm);

    const int lo = (blockIdx.x * NUNITS) / NCTA;
    const int hi = ((blockIdx.x + 1) * NUNITS) / NCTA;

    // --- prologue: all 512 threads stage A(row0) and B(col0) ---
    {
        const int row0 = lo / NBLK;
        const int col0 = lo - row0 * NBLK;
        for (int t = tid; t < 2048; t += 512) {      // A: 128 rows x 16 quads
            const int r = t >> 4, q = t & 15;
            uint4 vh = __ldg((const uint4*)(g_Ah + (size_t)(row0 * 128 + r) * NHID) + q);
            uint4 vl = __ldg((const uint4*)(g_Al + (size_t)(row0 * 128 + r) * NHID) + q);
            *(uint4*)(sm + OFF_AH + (r * LDA + q * 8) * 2) = vh;
            *(uint4*)(sm + OFF_AL + (r * LDA + q * 8) * 2) = vl;
        }
        for (int t = tid; t < 1024; t += 512) {      // B: 64 rows x 16 quads
            const int r = t >> 4, q = t & 15;
            uint4 vh = __ldg((const uint4*)(g_Bh + (size_t)(col0 * 64 + r) * NHID) + q);
            uint4 vl = __ldg((const uint4*)(g_Bl + (size_t)(col0 * 64 + r) * NHID) + q);
            *(uint4*)(sm + OFF_BH + (r * LDA + q * 8) * 2) = vh;
            *(uint4*)(sm + OFF_BL + (r * LDA + q * 8) * 2) = vl;
        }
    }
    __syncthreads();

    if (wid < 8) {
        // ===================== PRODUCER =====================
        const int wr = (wid >> 1) * 32;
        const int wc = (wid & 1)  * 32;

        const int g8 = lid & 7, q4 = lid >> 3;
        const int a_row  = g8 + ((q4 & 1) << 3);
        const int a_koff = (q4 >> 1) << 3;
        const int b_row  = g8 + ((q4 >> 1) << 3);
        const int b_koff = (q4 & 1) << 3;

        uint32_t aAddrH[2], aAddrL[2];
        #pragma unroll
        for (int mi = 0; mi < 2; mi++) {
            const uint32_t off = ((wr + mi * 16 + a_row) * LDA + a_koff) * 2;
            aAddrH[mi] = smB + OFF_AH + off;
            aAddrL[mi] = smB + OFF_AL + off;
        }
        uint32_t bAddrH[2], bAddrL[2];
        #pragma unroll
        for (int np = 0; np < 2; np++) {
            const uint32_t off = ((wc + np * 16 + b_row) * LDA + b_koff) * 2;
            bAddrH[np] = smB + OFF_BH + off;
            bAddrL[np] = smB + OFF_BL + off;
        }

        const int g = lid >> 2, tg = lid & 3;
        const int sb_row = tid >> 2;                 // 0..63 (tid<256)
        const int sb_q   = (tid & 3) * 4;

        int prow = lo / NBLK;

        for (int i = lo; i < hi; i++) {
            const int row = i / NBLK;
            const int li  = i - lo;
            const int s   = li & 1;

            if (row != prow) {                       // re-stage A (rare)
                for (int t = tid; t < 2048; t += 256) {
                    const int r = t >> 4, q = t & 15;
                    uint4 vh = __ldg((const uint4*)(g_Ah + (size_t)(row * 128 + r) * NHID) + q);
                    uint4 vl = __ldg((const uint4*)(g_Al + (size_t)(row * 128 + r) * NHID) + q);
                    *(uint4*)(sm + OFF_AH + (r * LDA + q * 8) * 2) = vh;
                    *(uint4*)(sm + OFF_AL + (r * LDA + q * 8) * 2) = vl;
                }
                prow = row;
            }
            BAR_SYNC(BID_PROD, 256);                 // A/B STS visible

            // register-prefetch next block's B
            const int inext = i + 1;
            int pcol = 0;
            if (inext < hi) pcol = inext - (inext / NBLK) * NBLK;
            uint4 pfh[4], pfl[4];
            {
                const uint4* bH = (const uint4*)(g_Bh + (size_t)(pcol * 64 + sb_row) * NHID);
                const uint4* bL = (const uint4*)(g_Bl + (size_t)(pcol * 64 + sb_row) * NHID);
                #pragma unroll
                for (int q = 0; q < 4; q++) {
                    pfh[q] = __ldg(bH + sb_q + q);
                    pfl[q] = __ldg(bL + sb_q + q);
                }
            }

            // MMA
            float acc[2][4][4];
            #pragma unroll
            for (int mi = 0; mi < 2; mi++)
                #pragma unroll
                for (int ni = 0; ni < 4; ni++)
                    #pragma unroll
                    for (int r = 0; r < 4; r++) acc[mi][ni][r] = 0.0f;

            #pragma unroll
            for (int ks = 0; ks < 8; ks++) {
                const uint32_t kb = ks * 32;
                uint32_t ah[2][4], al[2][4], bh[4][2], bl[4][2];
                #pragma unroll
                for (int mi = 0; mi < 2; mi++) {
                    ldsm_x4(ah[mi][0], ah[mi][1], ah[mi][2], ah[mi][3], aAddrH[mi] + kb);
                    ldsm_x4(al[mi][0], al[mi][1], al[mi][2], al[mi][3], aAddrL[mi] + kb);
                }
                #pragma unroll
                for (int np = 0; np < 2; np++) {
                    ldsm_x4(bh[2*np][0], bh[2*np][1], bh[2*np+1][0], bh[2*np+1][1],
                            bAddrH[np] + kb);
                    ldsm_x4(bl[2*np][0], bl[2*np][1], bl[2*np+1][0], bl[2*np+1][1],
                            bAddrL[np] + kb);
                }
                #pragma unroll
                for (int mi = 0; mi < 2; mi++)
                    #pragma unroll
                    for (int ni = 0; ni < 4; ni++)
                        mma16816(acc[mi][ni], ah[mi], bh[ni]);
                #pragma unroll
                for (int mi = 0; mi < 2; mi++)
                    #pragma unroll
                    for (int ni = 0; ni < 4; ni++)
                        mma16816(acc[mi][ni], ah[mi], bl[ni]);
                #pragma unroll
                for (int mi = 0; mi < 2; mi++)
                    #pragma unroll
                    for (int ni = 0; ni < 4; ni++)
                        mma16816(acc[mi][ni], al[mi], bh[ni]);
            }
            BAR_SYNC(BID_PROD, 256);                 // all producers done with B

            // STS next-B into B region
            if (inext < hi) {
                char* dH = sm + OFF_BH + (sb_row * LDA + sb_q * 8) * 2;
                char* dL = sm + OFF_BL + (sb_row * LDA + sb_q * 8) * 2;
                #pragma unroll
                for (int q = 0; q < 4; q++) {
                    *(uint4*)(dH + q * 16) = pfh[q];
                    *(uint4*)(dL + q * 16) = pfl[q];
                }
            }

            // wait slot free (released by consumer of block li-2)
            if (li >= 2) BAR_SYNC(BID_FREE0 + s, 512);

            // dump acc to slot s
            {
                float* slot = (float*)(sm + OFF_S0 + s * 51200);
                #pragma unroll
                for (int mi = 0; mi < 2; mi++) {
                    const int r0 = wr + mi * 16 + g;
                    #pragma unroll
                    for (int ni = 0; ni < 4; ni++) {
                        const int cl_loc = ((wc + ni * 8) >> 1) + tg;
                        *(float2*)(slot + r0 * LDS_SL + 2 * cl_loc) =
                            make_float2(acc[mi][ni][0], acc[mi][ni][1]);
                        *(float2*)(slot + (r0 + 8) * LDS_SL + 2 * cl_loc) =
                            make_float2(acc[mi][ni][2], acc[mi][ni][3]);
                    }
                }
            }
            BAR_ARRIVE(BID_FULL0 + s, 512);
        }
    } else {
        // ===================== CONSUMER =====================
        const int ctid = tid - 256;
        const int myrow = ctid >> 1;
        const int half  = ctid & 1;

        for (int i = lo; i < hi; i++) {
            const int row = i / NBLK;
            const int col = i - row * NBLK;
            const int li  = i - lo;
            const int s   = li & 1;
            const int cb  = col * 32;
            const int rbase = row * 128;
            float* slot = (float*)(sm + OFF_S0 + s * 51200);

            BAR_SYNC(BID_FULL0 + s, 512);            // wait acc ready

            float res[48];
            #pragma unroll
            for (int j = 0; j < 16; j++) {
                const int cll = half * 16 + j;
                const int cl  = cb + cll;
                const float2 a = *(const float2*)(slot + myrow * LDS_SL + 2 * cll);
                const float2 bp = __ldg(&g_b2p[cl < NCLUST ? cl : (NCLUST - 1)]);
                float e1 = fexp(a.x + bp.x);
                float e2 = fexp(a.y + bp.y);
                float inv = frcp(1.0f + e1 + e2);
                res[3 * j]     = inv;
                res[3 * j + 1] = e1 * inv;
                res[3 * j + 2] = e2 * inv;
            }
            BAR_SYNC(BID_CONS, 256);                 // reads done before overwrite

            {
                float* dst = slot + myrow * LDS_SL + half * 48;
                #pragma unroll
                for (int q = 0; q < 12; q++)
                    *(float4*)(dst + 4 * q) = make_float4(res[4 * q], res[4 * q + 1],
                                                          res[4 * q + 2], res[4 * q + 3]);
            }
            BAR_SYNC(BID_CONS, 256);                 // results visible

            // coalesced copy-out
            if (cb + 32 <= NCLUST) {
                for (int t = ctid; t < 128 * 24; t += 256) {
                    const int lr = t / 24, q = t - lr * 24;
                    float4 v = *(float4*)(slot + lr * LDS_SL + 4 * q);
                    __stcs((float4*)(out + (size_t)(rbase + lr) * NOUT + 3 * cb + 4 * q), v);
                }
            } else {
                for (int t = ctid; t < 128 * 12; t += 256) {
                    const int lr = t / 12, q = t - lr * 12;
                    float4 v = *(float4*)(slot + lr * LDS_SL + 4 * q);
                    __stcs((float4*)(out + (size_t)(rbase + lr) * NOUT + 3 * cb + 4 * q), v);
                }
            }
            BAR_ARRIVE(BID_FREE0 + s, 512);          // slot free
        }
    }
}

// ---------------------------------------------------------------------------
extern "C" void kernel_launch(void* const* d_in, const int* in_sizes, int n_in,
                              void* d_out, int out_size) {
    const float* z     = (const float*)d_in[0];
    const float* W1    = (const float*)d_in[1];
    const float* b1    = (const float*)d_in[2];
    const float* gamma = (const float*)d_in[3];
    const float* beta  = (const float*)d_in[4];
    const float* W2    = (const float*)d_in[5];
    const float* b2    = (const float*)d_in[6];
    float* out = (float*)d_out;

    k_init<<<1, 128>>>();
    k_h<<<BATCH / 128, 256>>>(z, W1, b1);
    k_bn<<<1, 128>>>(gamma, beta);
    k_split_h<<<(BATCH * NHID + 255) / 256, 256>>>();
    k_split_w<<<(NCC_PAD * NHID + 255) / 256, 256>>>(W2, b2);

    cudaFuncSetAttribute(k_gemm, cudaFuncAttributeMaxDynamicSharedMemorySize,
                         SMEM_DYN);
    k_gemm<<<NCTA, 512, SMEM_DYN>>>(out);            // 148 CTAs = 1 exact wave
}